// round 14
// baseline (speedup 1.0000x reference)
#include <cuda_runtime.h>
#include <stdint.h>

#define NB 32
#define NC 512
#define T_IN 1024
#define T_OUT 4096

#define CPB 8                    // channels per CTA -> grid = 2048
#define NT  256                  // threads per CTA
#define EPT (T_IN / NT)          // durations per thread in the scan = 4
#define NW  (NT / 32)            // warps per CTA = 8

// ---------------------------------------------------------------------------
// Fused kernel, TMA-store version. Each CTA = (batch, 8-channel group).
//   Phase A: scan durations, scatter run-length index map to smem (u16).
//   Phase B: per channel, gather enc row into a 16KB smem staging buffer
//            (STS only — no STG through L1tex), then ONE cp.async.bulk
//            shared->global per row. Double-buffered so gather(n+1) overlaps
//            the TMA drain of row n. Removes ~23us/SM of STG.128 issue cost
//            that bounded the R10 kernel.
// Durations int32-vs-int64 detected on-device (odd words all zero => int64).
// ---------------------------------------------------------------------------
__global__ __launch_bounds__(NT)
void length_regulate_kernel(const float* __restrict__ enc,
                            const int*   __restrict__ dur32,
                            float*       __restrict__ out) {
    __shared__ unsigned short sidx[T_OUT];             // 8 KB index map
    __shared__ __align__(16) float obuf[2][T_OUT];     // 2 x 16 KB staging
    __shared__ int wsum[NW];

    const int groups_per_b = NC / CPB;              // 64
    const int b  = blockIdx.x / groups_per_b;
    const int cg = blockIdx.x % groups_per_b;
    const int tid = threadIdx.x;

    // ---- dtype detection: OR of odd words in first 2048 int32s ----
    int odd = 0;
#pragma unroll
    for (int i = 0; i < T_IN / NT; ++i)
        odd |= dur32[2 * (i * NT + tid) + 1];
    const bool is32 = __syncthreads_or(odd) != 0;

    // ---- Phase A: scan + scatter (proven R10 logic) ----
    int d[EPT];
    {
        const int j0 = tid * EPT;
        if (is32) {
#pragma unroll
            for (int k = 0; k < EPT; ++k) d[k] = dur32[b * T_IN + j0 + k];
        } else {
#pragma unroll
            for (int k = 0; k < EPT; ++k) d[k] = dur32[(b * T_IN + j0 + k) * 2];
        }
    }
    int tot = 0;
    int pre[EPT];
#pragma unroll
    for (int k = 0; k < EPT; ++k) { pre[k] = tot; tot += d[k]; }

    const int lane = tid & 31;
    const int warp = tid >> 5;

    int incl = tot;
#pragma unroll
    for (int o = 1; o < 32; o <<= 1) {
        int n = __shfl_up_sync(0xffffffffu, incl, o);
        if (lane >= o) incl += n;
    }
    if (lane == 31) wsum[warp] = incl;
    __syncthreads();

    // all 32 lanes of warp 0 participate (partial-warp full-mask shfl hangs)
    if (warp == 0) {
        int w = (lane < NW) ? wsum[lane] : 0;
#pragma unroll
        for (int o = 1; o < 32; o <<= 1) {
            int n = __shfl_up_sync(0xffffffffu, w, o);
            if (lane >= o) w += n;
        }
        if (lane < NW) wsum[lane] = w;
    }
    __syncthreads();

    int base = (incl - tot) + (warp ? wsum[warp - 1] : 0);

    {
        const int j0 = tid * EPT;
#pragma unroll
        for (int k = 0; k < EPT; ++k) {
            const int s = base + pre[k];
            const int e = s + d[k];
            for (int t = s; t < e; ++t) sidx[t] = (unsigned short)(j0 + k);
        }
    }
    __syncthreads();

    // ---- Phase B: gather into smem, TMA bulk store per channel row ----
    const int c0 = cg * CPB;
    const size_t rowbase = (size_t)(b * NC + c0);

#pragma unroll 1
    for (int cc = 0; cc < CPB; ++cc) {
        const int buf = cc & 1;
        const float* __restrict__ erow = enc + (rowbase + cc) * T_IN;

        // reclaim this buffer: allow at most 1 bulk group still reading smem
        if (cc >= 2) {
            if (tid == 0)
                asm volatile("cp.async.bulk.wait_group.read 1;" ::: "memory");
            __syncthreads();
        }

        // gather 4096 floats into obuf[buf]; 4 float4 per thread
#pragma unroll
        for (int it = 0; it < (T_OUT / 4) / NT; ++it) {    // 4 iters
            const int g = it * NT + tid;                   // float4 group
            const uint2 p = *(const uint2*)(sidx + 4 * g); // 4 u16 indices
            float4 o;
            o.x = __ldg(erow + (p.x & 0xFFFF));
            o.y = __ldg(erow + (p.x >> 16));
            o.z = __ldg(erow + (p.y & 0xFFFF));
            o.w = __ldg(erow + (p.y >> 16));
            *(float4*)(obuf[buf] + 4 * g) = o;             // STS.128
        }
        __syncthreads();

        if (tid == 0) {
            asm volatile("fence.proxy.async.shared::cta;" ::: "memory");
            const uint32_t sptr =
                (uint32_t)__cvta_generic_to_shared(obuf[buf]);
            const float* gptr = out + (rowbase + cc) * T_OUT;
            asm volatile(
                "cp.async.bulk.global.shared::cta.bulk_group [%0], [%1], %2;"
                :: "l"(gptr), "r"(sptr), "r"((uint32_t)(T_OUT * 4))
                : "memory");
            asm volatile("cp.async.bulk.commit_group;" ::: "memory");
        }
    }

    // drain all bulk stores before exit
    if (tid == 0)
        asm volatile("cp.async.bulk.wait_group 0;" ::: "memory");
    __syncthreads();
}

// ---------------------------------------------------------------------------
extern "C" void kernel_launch(void* const* d_in, const int* in_sizes, int n_in,
                              void* d_out, int out_size) {
    const void* enc_p = d_in[0];
    const void* dur_p = d_in[1];
    if (n_in >= 2 && in_sizes[0] == NB * T_IN) {    // durations came first
        dur_p = d_in[0];
        enc_p = d_in[1];
    }
    length_regulate_kernel<<<NB * (NC / CPB), NT>>>(
        (const float*)enc_p, (const int*)dur_p, (float*)d_out);
}

// round 15
// speedup vs baseline: 1.3791x; 1.3791x over previous
#include <cuda_runtime.h>
#include <stdint.h>

#define NB 32
#define NC 512
#define T_IN 1024
#define T_OUT 4096

#define CPB 8                    // channels per CTA -> grid = 2048
#define NT  256                  // threads per CTA
#define EPT (T_IN / NT)          // durations per thread in the scan = 4
#define NW  (NT / 32)            // warps per CTA = 8

// ---------------------------------------------------------------------------
// Fused kernel (R10 structure + dual-channel MLP). CTA = (batch, 8 channels).
//   Phase A: scan durations, scatter run-length index map into smem (int32).
//   Phase B: gather TWO channel rows per iteration sharing one index vector:
//            8 independent LDGs + 2 independent STG.128s in flight per step
//            (2x the per-warp MLP of the 61us R10 kernel), index LDS halved.
// __launch_bounds__(256,5): 51-reg ceiling -> no spills (R13 lesson), 5
// CTAs/SM = 40 warps, same occupancy as R10 but double memory parallelism.
// Durations int32-vs-int64 detected on-device (odd words all zero => int64).
// ---------------------------------------------------------------------------
__global__ __launch_bounds__(NT, 5)
void length_regulate_kernel(const float* __restrict__ enc,
                            const int*   __restrict__ dur32,
                            float*       __restrict__ out) {
    const int groups_per_b = NC / CPB;              // 64
    const int b  = blockIdx.x / groups_per_b;
    const int cg = blockIdx.x % groups_per_b;
    const int tid = threadIdx.x;

    __shared__ int sidx[T_OUT];                     // 16 KB index map
    __shared__ int wsum[NW];

    // ---- dtype detection: OR of odd words in first 2048 int32s ----
    int odd = 0;
#pragma unroll
    for (int i = 0; i < T_IN / NT; ++i)
        odd |= dur32[2 * (i * NT + tid) + 1];
    const bool is32 = __syncthreads_or(odd) != 0;

    // ---- Phase A: scan + scatter (proven R10 logic) ----
    int d[EPT];
    {
        const int j0 = tid * EPT;
        if (is32) {
#pragma unroll
            for (int k = 0; k < EPT; ++k) d[k] = dur32[b * T_IN + j0 + k];
        } else {
#pragma unroll
            for (int k = 0; k < EPT; ++k) d[k] = dur32[(b * T_IN + j0 + k) * 2];
        }
    }
    int tot = 0;
    int pre[EPT];
#pragma unroll
    for (int k = 0; k < EPT; ++k) { pre[k] = tot; tot += d[k]; }

    const int lane = tid & 31;
    const int warp = tid >> 5;

    int incl = tot;
#pragma unroll
    for (int o = 1; o < 32; o <<= 1) {
        int n = __shfl_up_sync(0xffffffffu, incl, o);
        if (lane >= o) incl += n;
    }
    if (lane == 31) wsum[warp] = incl;
    __syncthreads();

    // all 32 lanes of warp 0 participate (partial-warp full-mask shfl hangs)
    if (warp == 0) {
        int w = (lane < NW) ? wsum[lane] : 0;
#pragma unroll
        for (int o = 1; o < 32; o <<= 1) {
            int n = __shfl_up_sync(0xffffffffu, w, o);
            if (lane >= o) w += n;
        }
        if (lane < NW) wsum[lane] = w;
    }
    __syncthreads();

    int base = (incl - tot) + (warp ? wsum[warp - 1] : 0);

    {
        const int j0 = tid * EPT;
#pragma unroll
        for (int k = 0; k < EPT; ++k) {
            const int s = base + pre[k];
            const int e = s + d[k];
            for (int t = s; t < e; ++t) sidx[t] = j0 + k;
        }
    }
    __syncthreads();

    // ---- Phase B: dual-channel gather, shared index, streaming stores ----
    const int c0 = cg * CPB;
    const size_t rowbase = (size_t)(b * NC + c0);
    const int4* __restrict__ si4 = (const int4*)sidx;

#pragma unroll
    for (int cp = 0; cp < CPB; cp += 2) {
        const float* __restrict__ erow0 = enc + (rowbase + cp) * T_IN;
        const float* __restrict__ erow1 = erow0 + T_IN;
        float4* __restrict__ orow0 = (float4*)(out + (rowbase + cp) * T_OUT);
        float4* __restrict__ orow1 = orow0 + T_OUT / 4;

#pragma unroll
        for (int it = 0; it < (T_OUT / 4) / NT; ++it) {   // 4 iters
            const int t4 = it * NT + tid;
            const int4 id = si4[t4];

            float4 a, c;                   // 8 independent loads in flight
            a.x = __ldg(erow0 + id.x);
            a.y = __ldg(erow0 + id.y);
            a.z = __ldg(erow0 + id.z);
            a.w = __ldg(erow0 + id.w);
            c.x = __ldg(erow1 + id.x);
            c.y = __ldg(erow1 + id.y);
            c.z = __ldg(erow1 + id.z);
            c.w = __ldg(erow1 + id.w);

            __stcs(orow0 + t4, a);
            __stcs(orow1 + t4, c);
        }
    }
}

// ---------------------------------------------------------------------------
extern "C" void kernel_launch(void* const* d_in, const int* in_sizes, int n_in,
                              void* d_out, int out_size) {
    const void* enc_p = d_in[0];
    const void* dur_p = d_in[1];
    if (n_in >= 2 && in_sizes[0] == NB * T_IN) {    // durations came first
        dur_p = d_in[0];
        enc_p = d_in[1];
    }
    length_regulate_kernel<<<NB * (NC / CPB), NT>>>(
        (const float*)enc_p, (const int*)dur_p, (float*)d_out);
}